// round 7
// baseline (speedup 1.0000x reference)
#include <cuda_runtime.h>
#include <cuda_fp16.h>

#define NN 50000
#define NE 800000
#define FIN 16
#define FE 8
#define HD 8
#define NG 512

// Scratch (allocation-free: __device__ globals).
// g_Yh: per-node factor table in FP16, layout [n][o][a] as half:
//       row = 64 halves = 128 B = ONE cache line. Lane r's uint4 at
//       offset n*128 + r*16 covers o=r, a=0..7 completely (in-lane dot).
// g_base: per-node base term base[n][o], fp32 (precision-critical path).
// g_agg:  scatter accumulators, fp32, natural order [layer][n*8+o].
__device__ __half2 g_Yh[NN * 32];
__device__ float   g_base[NN * HD];
__device__ float   g_agg[2][NN * HD];

// Layer-1 per-node precompute, thread per (n,o). Also zeroes agg and seeds out.
//   Y1[n][o][a] = sum_i x[n,i] * We1[a, i*8+o]          (stored fp16)
//   base1[n][o] = b1[o] + sum_i x[n,i] * (root1[i,o] + be1[i*8+o])
__global__ void k_node1(const float* __restrict__ x, const float* __restrict__ We1,
                        const float* __restrict__ be1, const float* __restrict__ root1,
                        const float* __restrict__ b1, const float* __restrict__ blast,
                        float* __restrict__ out) {
    __shared__ float sW[FIN * HD * HD];   // [i][o][a]
    __shared__ float sWc[FIN * HD];       // root1 + be1 : [i][o]
    for (int t = threadIdx.x; t < FIN * 64; t += blockDim.x) {
        int i = t >> 6, o = (t >> 3) & 7, a = t & 7;
        sW[t] = We1[a * (FIN * HD) + i * HD + o];
    }
    for (int t = threadIdx.x; t < FIN * HD; t += blockDim.x)
        sWc[t] = root1[t] + be1[t];
    __syncthreads();

    int gid = blockIdx.x * blockDim.x + threadIdx.x;
    if (gid < NG) out[gid] = blast[0];
    if (gid < NN * 2) {
        float4 z = make_float4(0.f, 0.f, 0.f, 0.f);
        ((float4*)g_agg[0])[gid] = z;
        ((float4*)g_agg[1])[gid] = z;
    }
    int n = gid >> 3, o = gid & 7;
    if (n >= NN) return;

    float xv[FIN];
    const float4* xp = (const float4*)(x + n * FIN);
    #pragma unroll
    for (int q = 0; q < 4; q++) {
        float4 v = xp[q];
        xv[q * 4 + 0] = v.x; xv[q * 4 + 1] = v.y;
        xv[q * 4 + 2] = v.z; xv[q * 4 + 3] = v.w;
    }

    float4 acc0 = make_float4(0.f, 0.f, 0.f, 0.f);   // a = 0..3
    float4 acc1 = make_float4(0.f, 0.f, 0.f, 0.f);   // a = 4..7
    float bacc = __ldg(b1 + o);
    const float4* sW4 = (const float4*)sW;
    #pragma unroll
    for (int i = 0; i < FIN; i++) {
        float xi = xv[i];
        float4 w0 = sW4[(i * HD + o) * 2 + 0];
        float4 w1 = sW4[(i * HD + o) * 2 + 1];
        acc0.x = fmaf(xi, w0.x, acc0.x); acc0.y = fmaf(xi, w0.y, acc0.y);
        acc0.z = fmaf(xi, w0.z, acc0.z); acc0.w = fmaf(xi, w0.w, acc0.w);
        acc1.x = fmaf(xi, w1.x, acc1.x); acc1.y = fmaf(xi, w1.y, acc1.y);
        acc1.z = fmaf(xi, w1.z, acc1.z); acc1.w = fmaf(xi, w1.w, acc1.w);
        bacc = fmaf(xi, sWc[i * HD + o], bacc);
    }

    __half2 hy[4];
    hy[0] = __floats2half2_rn(acc0.x, acc0.y);
    hy[1] = __floats2half2_rn(acc0.z, acc0.w);
    hy[2] = __floats2half2_rn(acc1.x, acc1.y);
    hy[3] = __floats2half2_rn(acc1.z, acc1.w);
    *(uint4*)(g_Yh + n * 32 + o * 4) = *(const uint4*)hy;
    g_base[gid] = bacc;
}

// Edge scatter: 8 lanes/edge, 2 edges/thread (e and e+NE/2).
// Lane r loads ONE uint4 (16B) = full fp16 Y row slice for o=r:
// 1 L1tex wavefront per edge (floor for a 128B row). Dot fully in-lane.
// 3 independent shfls gather m[r+1..r+3] into lanes r=0,4 -> 2 red.v4/edge.
// launch_bounds(256,5): reg budget 51 (full 2-edge front-batch stays in
// flight, MLP~10) while keeping 40 resident warps (83% occ) for latency
// hiding — the middle of the occ/MLP frontier that R5 (64w/32r) and
// R6 (32w/38r) bracketed.
__global__ void __launch_bounds__(256, 5)
k_edge(const int* __restrict__ ei, const float* __restrict__ ea, int layer) {
    int gid = blockIdx.x * blockDim.x + threadIdx.x;
    int r = gid & 7;
    int e0 = gid >> 3;            // [0, NE/2)
    int e1 = e0 + (NE / 2);

    // src loads first: they head the dependent src->Y chain.
    int src0 = __ldg(ei + e0);
    int src1 = __ldg(ei + e1);
    int dst0 = __ldg(ei + NE + e0);
    int dst1 = __ldg(ei + NE + e1);
    // independent ea loads fill the shadow of the src loads
    float4 ea00 = __ldg((const float4*)(ea + e0 * FE));
    float4 ea01 = __ldg((const float4*)(ea + e0 * FE + 4));
    float4 ea10 = __ldg((const float4*)(ea + e1 * FE));
    float4 ea11 = __ldg((const float4*)(ea + e1 * FE + 4));
    // Y gathers: written by the preceding kernel, read-only here -> .nc path ok
    uint4 yq0 = __ldg((const uint4*)(g_Yh + src0 * 32 + r * 4));
    uint4 yq1 = __ldg((const uint4*)(g_Yh + src1 * 32 + r * 4));

    const __half2* yh0 = (const __half2*)&yq0;
    const __half2* yh1 = (const __half2*)&yq1;
    float2 f00 = __half22float2(yh0[0]), f01 = __half22float2(yh0[1]);
    float2 f02 = __half22float2(yh0[2]), f03 = __half22float2(yh0[3]);
    float2 f10 = __half22float2(yh1[0]), f11 = __half22float2(yh1[1]);
    float2 f12 = __half22float2(yh1[2]), f13 = __half22float2(yh1[3]);

    float m0 = ea00.x * f00.x + ea00.y * f00.y + ea00.z * f01.x + ea00.w * f01.y
             + ea01.x * f02.x + ea01.y * f02.y + ea01.z * f03.x + ea01.w * f03.y;
    float m1 = ea10.x * f10.x + ea10.y * f10.y + ea10.z * f11.x + ea10.w * f11.y
             + ea11.x * f12.x + ea11.y * f12.y + ea11.z * f13.x + ea11.w * f13.y;

    const unsigned FULL = 0xffffffffu;
    int lane = threadIdx.x & 31;
    // 3 independent depth-1 shuffles; consumers (r=0,4) read lanes +1..+3
    // which stay inside the same 8-lane edge group.
    float m0a = __shfl_sync(FULL, m0, (lane + 1) & 31);
    float m0b = __shfl_sync(FULL, m0, (lane + 2) & 31);
    float m0c = __shfl_sync(FULL, m0, (lane + 3) & 31);
    float m1a = __shfl_sync(FULL, m1, (lane + 1) & 31);
    float m1b = __shfl_sync(FULL, m1, (lane + 2) & 31);
    float m1c = __shfl_sync(FULL, m1, (lane + 3) & 31);

    if ((r & 3) == 0) {
        float* p0 = g_agg[layer] + dst0 * HD + r;
        asm volatile("red.global.add.v4.f32 [%0], {%1, %2, %3, %4};"
                     :: "l"(p0), "f"(m0), "f"(m0a), "f"(m0b), "f"(m0c) : "memory");
        float* p1 = g_agg[layer] + dst1 * HD + r;
        asm volatile("red.global.add.v4.f32 [%0], {%1, %2, %3, %4};"
                     :: "l"(p1), "f"(m1), "f"(m1a), "f"(m1b), "f"(m1c) : "memory");
    }
}

// h1 = relu(agg1 + base1); layer-2 per-node precompute (thread per (n,o)).
//   Y2[n][o][a] = sum_i h1[i] * We2[a, i*8+o]   (stored fp16)
//   base2[n][o] = b2[o] + sum_i h1[i] * (root2[i,o] + be2[i*8+o])
__global__ void k_node2(const float* __restrict__ We2, const float* __restrict__ be2,
                        const float* __restrict__ root2, const float* __restrict__ b2) {
    __shared__ float sW[HD * HD * HD];    // [i][o][a]
    __shared__ float sWc[HD * HD];        // root2 + be2 : [i][o]
    for (int t = threadIdx.x; t < HD * 64; t += blockDim.x) {
        int i = t >> 6, o = (t >> 3) & 7, a = t & 7;
        sW[t] = We2[a * (HD * HD) + i * HD + o];
    }
    for (int t = threadIdx.x; t < HD * HD; t += blockDim.x)
        sWc[t] = root2[t] + be2[t];
    __syncthreads();

    int gid = blockIdx.x * blockDim.x + threadIdx.x;
    int n = gid >> 3, o = gid & 7;
    if (n >= NN) return;

    float h[HD];
    {
        const float4* ap = (const float4*)(g_agg[0] + n * HD);
        const float4* cp = (const float4*)(g_base + n * HD);
        float4 a0 = ap[0], a1 = ap[1], c0 = cp[0], c1 = cp[1];
        h[0] = fmaxf(a0.x + c0.x, 0.f); h[1] = fmaxf(a0.y + c0.y, 0.f);
        h[2] = fmaxf(a0.z + c0.z, 0.f); h[3] = fmaxf(a0.w + c0.w, 0.f);
        h[4] = fmaxf(a1.x + c1.x, 0.f); h[5] = fmaxf(a1.y + c1.y, 0.f);
        h[6] = fmaxf(a1.z + c1.z, 0.f); h[7] = fmaxf(a1.w + c1.w, 0.f);
    }
    __syncwarp();   // all reads of g_base[n][*] done before warp-mates overwrite

    float4 acc0 = make_float4(0.f, 0.f, 0.f, 0.f);
    float4 acc1 = make_float4(0.f, 0.f, 0.f, 0.f);
    float bacc = __ldg(b2 + o);
    const float4* sW4 = (const float4*)sW;
    #pragma unroll
    for (int i = 0; i < HD; i++) {
        float hi = h[i];
        float4 w0 = sW4[(i * HD + o) * 2 + 0];
        float4 w1 = sW4[(i * HD + o) * 2 + 1];
        acc0.x = fmaf(hi, w0.x, acc0.x); acc0.y = fmaf(hi, w0.y, acc0.y);
        acc0.z = fmaf(hi, w0.z, acc0.z); acc0.w = fmaf(hi, w0.w, acc0.w);
        acc1.x = fmaf(hi, w1.x, acc1.x); acc1.y = fmaf(hi, w1.y, acc1.y);
        acc1.z = fmaf(hi, w1.z, acc1.z); acc1.w = fmaf(hi, w1.w, acc1.w);
        bacc = fmaf(hi, sWc[i * HD + o], bacc);
    }

    __half2 hy[4];
    hy[0] = __floats2half2_rn(acc0.x, acc0.y);
    hy[1] = __floats2half2_rn(acc0.z, acc0.w);
    hy[2] = __floats2half2_rn(acc1.x, acc1.y);
    hy[3] = __floats2half2_rn(acc1.z, acc1.w);
    *(uint4*)(g_Yh + n * 32 + o * 4) = *(const uint4*)hy;
    g_base[gid] = bacc;
}

// h2 = relu(agg2 + base2); out[batch[n]] += sum_o h2[o]*Wlast[o].
// batch is SORTED -> warp-segmented shfl reduction, one atomic per
// (warp, graph-id) run instead of one per node (50K -> ~2K atomics).
__global__ void k_pool(const int* __restrict__ batch, const float* __restrict__ Wlast,
                       float* __restrict__ out) {
    int n = blockIdx.x * blockDim.x + threadIdx.x;
    int lane = threadIdx.x & 31;
    float s = 0.f;
    int bid = -1;
    if (n < NN) {
        bid = batch[n];
        const float4* ap = (const float4*)(g_agg[1] + n * HD);
        const float4* cp = (const float4*)(g_base + n * HD);
        float4 a0 = ap[0], a1 = ap[1], c0 = cp[0], c1 = cp[1];
        s = fmaxf(a0.x + c0.x, 0.f) * __ldg(Wlast + 0)
          + fmaxf(a0.y + c0.y, 0.f) * __ldg(Wlast + 1)
          + fmaxf(a0.z + c0.z, 0.f) * __ldg(Wlast + 2)
          + fmaxf(a0.w + c0.w, 0.f) * __ldg(Wlast + 3)
          + fmaxf(a1.x + c1.x, 0.f) * __ldg(Wlast + 4)
          + fmaxf(a1.y + c1.y, 0.f) * __ldg(Wlast + 5)
          + fmaxf(a1.z + c1.z, 0.f) * __ldg(Wlast + 6)
          + fmaxf(a1.w + c1.w, 0.f) * __ldg(Wlast + 7);
    }
    const unsigned FULL = 0xffffffffu;
    int bprev = __shfl_up_sync(FULL, bid, 1);
    // segmented suffix-sum over contiguous equal-bid runs (batch sorted)
    #pragma unroll
    for (int d = 1; d < 32; d <<= 1) {
        float t = __shfl_down_sync(FULL, s, d);
        int  tb = __shfl_down_sync(FULL, bid, d);
        if (lane + d < 32 && tb == bid) s += t;
    }
    bool leader = (n < NN) && (lane == 0 || bprev != bid);
    if (leader) atomicAdd(out + bid, s);
}

extern "C" void kernel_launch(void* const* d_in, const int* in_sizes, int n_in,
                              void* d_out, int out_size) {
    const float* x     = (const float*)d_in[0];
    const int*   ei    = (const int*)  d_in[1];
    const float* ea    = (const float*)d_in[2];
    const int*   batch = (const int*)  d_in[3];
    const float* We1   = (const float*)d_in[4];
    const float* be1   = (const float*)d_in[5];
    const float* root1 = (const float*)d_in[6];
    const float* b1    = (const float*)d_in[7];
    const float* We2   = (const float*)d_in[8];
    const float* be2   = (const float*)d_in[9];
    const float* root2 = (const float*)d_in[10];
    const float* b2    = (const float*)d_in[11];
    const float* Wlast = (const float*)d_in[12];
    const float* blast = (const float*)d_in[13];
    float* out = (float*)d_out;

    k_node1<<<(NN * HD + 255) / 256, 256>>>(x, We1, be1, root1, b1, blast, out);
    k_edge <<<(NE / 2) * 8 / 256, 256>>>(ei, ea, 0);
    k_node2<<<(NN * HD + 255) / 256, 256>>>(We2, be2, root2, b2);
    k_edge <<<(NE / 2) * 8 / 256, 256>>>(ei, ea, 1);
    k_pool <<<(NN + 255) / 256, 256>>>(batch, Wlast, out);
}

// round 8
// speedup vs baseline: 1.0504x; 1.0504x over previous
#include <cuda_runtime.h>
#include <cuda_fp16.h>

#define NN 50000
#define NE 800000
#define FIN 16
#define FE 8
#define HD 8
#define NG 512

// Scratch (allocation-free: __device__ globals).
// g_Yh: per-node factor table in FP16, layout [n][o][a] as half:
//       row = 64 halves = 128 B = ONE cache line. Lane r's uint4 at
//       offset n*128 + r*16 covers o=r, a=0..7 completely (in-lane dot).
// g_base: per-node base term base[n][o], fp32 (precision-critical path).
// g_agg:  scatter accumulators, fp32, natural order [layer][n*8+o].
__device__ __half2 g_Yh[NN * 32];
__device__ float   g_base[NN * HD];
__device__ float   g_agg[2][NN * HD];

// Layer-1 per-node precompute, thread per (n,o). Also zeroes agg and seeds out.
__global__ void k_node1(const float* __restrict__ x, const float* __restrict__ We1,
                        const float* __restrict__ be1, const float* __restrict__ root1,
                        const float* __restrict__ b1, const float* __restrict__ blast,
                        float* __restrict__ out) {
    __shared__ float sW[FIN * HD * HD];   // [i][o][a]
    __shared__ float sWc[FIN * HD];       // root1 + be1 : [i][o]
    for (int t = threadIdx.x; t < FIN * 64; t += blockDim.x) {
        int i = t >> 6, o = (t >> 3) & 7, a = t & 7;
        sW[t] = We1[a * (FIN * HD) + i * HD + o];
    }
    for (int t = threadIdx.x; t < FIN * HD; t += blockDim.x)
        sWc[t] = root1[t] + be1[t];
    __syncthreads();

    int gid = blockIdx.x * blockDim.x + threadIdx.x;
    if (gid < NG) out[gid] = blast[0];
    if (gid < NN * 2) {
        float4 z = make_float4(0.f, 0.f, 0.f, 0.f);
        ((float4*)g_agg[0])[gid] = z;
        ((float4*)g_agg[1])[gid] = z;
    }
    int n = gid >> 3, o = gid & 7;
    if (n >= NN) return;

    float xv[FIN];
    const float4* xp = (const float4*)(x + n * FIN);
    #pragma unroll
    for (int q = 0; q < 4; q++) {
        float4 v = xp[q];
        xv[q * 4 + 0] = v.x; xv[q * 4 + 1] = v.y;
        xv[q * 4 + 2] = v.z; xv[q * 4 + 3] = v.w;
    }

    float4 acc0 = make_float4(0.f, 0.f, 0.f, 0.f);   // a = 0..3
    float4 acc1 = make_float4(0.f, 0.f, 0.f, 0.f);   // a = 4..7
    float bacc = __ldg(b1 + o);
    const float4* sW4 = (const float4*)sW;
    #pragma unroll
    for (int i = 0; i < FIN; i++) {
        float xi = xv[i];
        float4 w0 = sW4[(i * HD + o) * 2 + 0];
        float4 w1 = sW4[(i * HD + o) * 2 + 1];
        acc0.x = fmaf(xi, w0.x, acc0.x); acc0.y = fmaf(xi, w0.y, acc0.y);
        acc0.z = fmaf(xi, w0.z, acc0.z); acc0.w = fmaf(xi, w0.w, acc0.w);
        acc1.x = fmaf(xi, w1.x, acc1.x); acc1.y = fmaf(xi, w1.y, acc1.y);
        acc1.z = fmaf(xi, w1.z, acc1.z); acc1.w = fmaf(xi, w1.w, acc1.w);
        bacc = fmaf(xi, sWc[i * HD + o], bacc);
    }

    __half2 hy[4];
    hy[0] = __floats2half2_rn(acc0.x, acc0.y);
    hy[1] = __floats2half2_rn(acc0.z, acc0.w);
    hy[2] = __floats2half2_rn(acc1.x, acc1.y);
    hy[3] = __floats2half2_rn(acc1.z, acc1.w);
    *(uint4*)(g_Yh + n * 32 + o * 4) = *(const uint4*)hy;
    g_base[gid] = bacc;
}

// Edge scatter: 8 lanes/edge, FOUR edges/thread (t, t+Q, t+2Q, t+3Q).
// Lane r loads ONE uint4 = full fp16 Y row for o=r: 1 L1tex wavefront/edge
// (floor). All 20 gather loads front-batched -> MLP ~20 per thread; with
// launch_bounds(256,4) the 64-reg budget keeps them all in flight.
// Per edge: 3 depth-1 shfls gather m[r+1..3] into lanes r=0,4 -> 2 red.v4.
__global__ void __launch_bounds__(256, 4)
k_edge(const int* __restrict__ ei, const float* __restrict__ ea, int layer) {
    const int Q = NE / 4;
    int gid = blockIdx.x * blockDim.x + threadIdx.x;
    int r = gid & 7;
    int t = gid >> 3;             // [0, NE/4)
    int e0 = t, e1 = t + Q, e2 = t + 2 * Q, e3 = t + 3 * Q;

    // src loads first: they head the dependent src->Y chains.
    int src0 = __ldg(ei + e0);
    int src1 = __ldg(ei + e1);
    int src2 = __ldg(ei + e2);
    int src3 = __ldg(ei + e3);
    int dst0 = __ldg(ei + NE + e0);
    int dst1 = __ldg(ei + NE + e1);
    int dst2 = __ldg(ei + NE + e2);
    int dst3 = __ldg(ei + NE + e3);
    // independent ea loads fill the shadow of the src loads
    float4 a00 = __ldg((const float4*)(ea + e0 * FE));
    float4 a01 = __ldg((const float4*)(ea + e0 * FE + 4));
    float4 a10 = __ldg((const float4*)(ea + e1 * FE));
    float4 a11 = __ldg((const float4*)(ea + e1 * FE + 4));
    float4 a20 = __ldg((const float4*)(ea + e2 * FE));
    float4 a21 = __ldg((const float4*)(ea + e2 * FE + 4));
    float4 a30 = __ldg((const float4*)(ea + e3 * FE));
    float4 a31 = __ldg((const float4*)(ea + e3 * FE + 4));
    // dependent Y gathers (read-only in this kernel -> .nc path)
    uint4 yq0 = __ldg((const uint4*)(g_Yh + src0 * 32 + r * 4));
    uint4 yq1 = __ldg((const uint4*)(g_Yh + src1 * 32 + r * 4));
    uint4 yq2 = __ldg((const uint4*)(g_Yh + src2 * 32 + r * 4));
    uint4 yq3 = __ldg((const uint4*)(g_Yh + src3 * 32 + r * 4));

    const unsigned FULL = 0xffffffffu;
    int lane = threadIdx.x & 31;
    float* aggL = g_agg[layer];

    // per-edge: dot (fp32 accum from fp16 Y), 3 shfls, 2 predicated red.v4
    #define EDGE_EMIT(yq, A0, A1, dst)                                          \
    {                                                                           \
        const __half2* yh = (const __half2*)&(yq);                              \
        float2 q0 = __half22float2(yh[0]), q1 = __half22float2(yh[1]);          \
        float2 q2 = __half22float2(yh[2]), q3 = __half22float2(yh[3]);          \
        float m = (A0).x * q0.x + (A0).y * q0.y + (A0).z * q1.x + (A0).w * q1.y \
                + (A1).x * q2.x + (A1).y * q2.y + (A1).z * q3.x + (A1).w * q3.y;\
        float ma = __shfl_sync(FULL, m, (lane + 1) & 31);                       \
        float mb = __shfl_sync(FULL, m, (lane + 2) & 31);                       \
        float mc = __shfl_sync(FULL, m, (lane + 3) & 31);                       \
        if ((r & 3) == 0) {                                                     \
            float* p = aggL + (dst) * HD + r;                                   \
            asm volatile("red.global.add.v4.f32 [%0], {%1, %2, %3, %4};"        \
                         :: "l"(p), "f"(m), "f"(ma), "f"(mb), "f"(mc)           \
                         : "memory");                                           \
        }                                                                       \
    }

    EDGE_EMIT(yq0, a00, a01, dst0)
    EDGE_EMIT(yq1, a10, a11, dst1)
    EDGE_EMIT(yq2, a20, a21, dst2)
    EDGE_EMIT(yq3, a30, a31, dst3)
    #undef EDGE_EMIT
}

// h1 = relu(agg1 + base1); layer-2 per-node precompute (thread per (n,o)).
__global__ void k_node2(const float* __restrict__ We2, const float* __restrict__ be2,
                        const float* __restrict__ root2, const float* __restrict__ b2) {
    __shared__ float sW[HD * HD * HD];    // [i][o][a]
    __shared__ float sWc[HD * HD];        // root2 + be2 : [i][o]
    for (int t = threadIdx.x; t < HD * 64; t += blockDim.x) {
        int i = t >> 6, o = (t >> 3) & 7, a = t & 7;
        sW[t] = We2[a * (HD * HD) + i * HD + o];
    }
    for (int t = threadIdx.x; t < HD * HD; t += blockDim.x)
        sWc[t] = root2[t] + be2[t];
    __syncthreads();

    int gid = blockIdx.x * blockDim.x + threadIdx.x;
    int n = gid >> 3, o = gid & 7;
    if (n >= NN) return;

    float h[HD];
    {
        const float4* ap = (const float4*)(g_agg[0] + n * HD);
        const float4* cp = (const float4*)(g_base + n * HD);
        float4 a0 = ap[0], a1 = ap[1], c0 = cp[0], c1 = cp[1];
        h[0] = fmaxf(a0.x + c0.x, 0.f); h[1] = fmaxf(a0.y + c0.y, 0.f);
        h[2] = fmaxf(a0.z + c0.z, 0.f); h[3] = fmaxf(a0.w + c0.w, 0.f);
        h[4] = fmaxf(a1.x + c1.x, 0.f); h[5] = fmaxf(a1.y + c1.y, 0.f);
        h[6] = fmaxf(a1.z + c1.z, 0.f); h[7] = fmaxf(a1.w + c1.w, 0.f);
    }
    __syncwarp();   // all reads of g_base[n][*] done before warp-mates overwrite

    float4 acc0 = make_float4(0.f, 0.f, 0.f, 0.f);
    float4 acc1 = make_float4(0.f, 0.f, 0.f, 0.f);
    float bacc = __ldg(b2 + o);
    const float4* sW4 = (const float4*)sW;
    #pragma unroll
    for (int i = 0; i < HD; i++) {
        float hi = h[i];
        float4 w0 = sW4[(i * HD + o) * 2 + 0];
        float4 w1 = sW4[(i * HD + o) * 2 + 1];
        acc0.x = fmaf(hi, w0.x, acc0.x); acc0.y = fmaf(hi, w0.y, acc0.y);
        acc0.z = fmaf(hi, w0.z, acc0.z); acc0.w = fmaf(hi, w0.w, acc0.w);
        acc1.x = fmaf(hi, w1.x, acc1.x); acc1.y = fmaf(hi, w1.y, acc1.y);
        acc1.z = fmaf(hi, w1.z, acc1.z); acc1.w = fmaf(hi, w1.w, acc1.w);
        bacc = fmaf(hi, sWc[i * HD + o], bacc);
    }

    __half2 hy[4];
    hy[0] = __floats2half2_rn(acc0.x, acc0.y);
    hy[1] = __floats2half2_rn(acc0.z, acc0.w);
    hy[2] = __floats2half2_rn(acc1.x, acc1.y);
    hy[3] = __floats2half2_rn(acc1.z, acc1.w);
    *(uint4*)(g_Yh + n * 32 + o * 4) = *(const uint4*)hy;
    g_base[gid] = bacc;
}

// h2 = relu(agg2 + base2); out[batch[n]] += sum_o h2[o]*Wlast[o].
// batch is SORTED -> warp-segmented shfl reduction, one atomic per
// (warp, graph-id) run instead of one per node.
__global__ void k_pool(const int* __restrict__ batch, const float* __restrict__ Wlast,
                       float* __restrict__ out) {
    int n = blockIdx.x * blockDim.x + threadIdx.x;
    int lane = threadIdx.x & 31;
    float s = 0.f;
    int bid = -1;
    if (n < NN) {
        bid = batch[n];
        const float4* ap = (const float4*)(g_agg[1] + n * HD);
        const float4* cp = (const float4*)(g_base + n * HD);
        float4 a0 = ap[0], a1 = ap[1], c0 = cp[0], c1 = cp[1];
        s = fmaxf(a0.x + c0.x, 0.f) * __ldg(Wlast + 0)
          + fmaxf(a0.y + c0.y, 0.f) * __ldg(Wlast + 1)
          + fmaxf(a0.z + c0.z, 0.f) * __ldg(Wlast + 2)
          + fmaxf(a0.w + c0.w, 0.f) * __ldg(Wlast + 3)
          + fmaxf(a1.x + c1.x, 0.f) * __ldg(Wlast + 4)
          + fmaxf(a1.y + c1.y, 0.f) * __ldg(Wlast + 5)
          + fmaxf(a1.z + c1.z, 0.f) * __ldg(Wlast + 6)
          + fmaxf(a1.w + c1.w, 0.f) * __ldg(Wlast + 7);
    }
    const unsigned FULL = 0xffffffffu;
    int bprev = __shfl_up_sync(FULL, bid, 1);
    // segmented suffix-sum over contiguous equal-bid runs (batch sorted)
    #pragma unroll
    for (int d = 1; d < 32; d <<= 1) {
        float t = __shfl_down_sync(FULL, s, d);
        int  tb = __shfl_down_sync(FULL, bid, d);
        if (lane + d < 32 && tb == bid) s += t;
    }
    bool leader = (n < NN) && (lane == 0 || bprev != bid);
    if (leader) atomicAdd(out + bid, s);
}

extern "C" void kernel_launch(void* const* d_in, const int* in_sizes, int n_in,
                              void* d_out, int out_size) {
    const float* x     = (const float*)d_in[0];
    const int*   ei    = (const int*)  d_in[1];
    const float* ea    = (const float*)d_in[2];
    const int*   batch = (const int*)  d_in[3];
    const float* We1   = (const float*)d_in[4];
    const float* be1   = (const float*)d_in[5];
    const float* root1 = (const float*)d_in[6];
    const float* b1    = (const float*)d_in[7];
    const float* We2   = (const float*)d_in[8];
    const float* be2   = (const float*)d_in[9];
    const float* root2 = (const float*)d_in[10];
    const float* b2    = (const float*)d_in[11];
    const float* Wlast = (const float*)d_in[12];
    const float* blast = (const float*)d_in[13];
    float* out = (float*)d_out;

    k_node1<<<(NN * HD + 255) / 256, 256>>>(x, We1, be1, root1, b1, blast, out);
    k_edge <<<(NE / 4) * 8 / 256, 256>>>(ei, ea, 0);
    k_node2<<<(NN * HD + 255) / 256, 256>>>(We2, be2, root2, b2);
    k_edge <<<(NE / 4) * 8 / 256, 256>>>(ei, ea, 1);
    k_pool <<<(NN + 255) / 256, 256>>>(batch, Wlast, out);
}

// round 10
// speedup vs baseline: 1.0840x; 1.0320x over previous
#include <cuda_runtime.h>
#include <cuda_fp16.h>

#define NN 50000
#define NE 800000
#define FIN 16
#define FE 8
#define HD 8
#define NG 512

// Scratch (allocation-free: __device__ globals).
// g_Yh: per-node factor table in FP16, layout [n][o][a] as half:
//       row = 64 halves = 128 B = ONE cache line. Lane r's uint4 at
//       offset n*128 + r*16 covers o=r, a=0..7 completely (in-lane dot).
// g_base: per-node base term base[n][o], fp32 (precision-critical path).
// g_agg:  scatter accumulators, fp32, natural order [layer][n*8+o].
__device__ __half2 g_Yh[NN * 32];
__device__ float   g_base[NN * HD];
__device__ float   g_agg[2][NN * HD];

// Layer-1 per-node precompute, thread per (n,o). Zeroes agg[0], seeds out.
__global__ void k_node1(const float* __restrict__ x, const float* __restrict__ We1,
                        const float* __restrict__ be1, const float* __restrict__ root1,
                        const float* __restrict__ b1, const float* __restrict__ blast,
                        float* __restrict__ out) {
    __shared__ float sW[FIN * HD * HD];   // [i][o][a]
    __shared__ float sWc[FIN * HD];       // root1 + be1 : [i][o]
    for (int t = threadIdx.x; t < FIN * 64; t += blockDim.x) {
        int i = t >> 6, o = (t >> 3) & 7, a = t & 7;
        sW[t] = We1[a * (FIN * HD) + i * HD + o];
    }
    for (int t = threadIdx.x; t < FIN * HD; t += blockDim.x)
        sWc[t] = root1[t] + be1[t];
    __syncthreads();

    int gid = blockIdx.x * blockDim.x + threadIdx.x;
    if (gid < NG) out[gid] = blast[0];
    if (gid < NN * 2)
        ((float4*)g_agg[0])[gid] = make_float4(0.f, 0.f, 0.f, 0.f);
    int n = gid >> 3, o = gid & 7;
    if (n >= NN) return;

    float xv[FIN];
    const float4* xp = (const float4*)(x + n * FIN);
    #pragma unroll
    for (int q = 0; q < 4; q++) {
        float4 v = xp[q];
        xv[q * 4 + 0] = v.x; xv[q * 4 + 1] = v.y;
        xv[q * 4 + 2] = v.z; xv[q * 4 + 3] = v.w;
    }

    float4 acc0 = make_float4(0.f, 0.f, 0.f, 0.f);   // a = 0..3
    float4 acc1 = make_float4(0.f, 0.f, 0.f, 0.f);   // a = 4..7
    float bacc = __ldg(b1 + o);
    const float4* sW4 = (const float4*)sW;
    #pragma unroll
    for (int i = 0; i < FIN; i++) {
        float xi = xv[i];
        float4 w0 = sW4[(i * HD + o) * 2 + 0];
        float4 w1 = sW4[(i * HD + o) * 2 + 1];
        acc0.x = fmaf(xi, w0.x, acc0.x); acc0.y = fmaf(xi, w0.y, acc0.y);
        acc0.z = fmaf(xi, w0.z, acc0.z); acc0.w = fmaf(xi, w0.w, acc0.w);
        acc1.x = fmaf(xi, w1.x, acc1.x); acc1.y = fmaf(xi, w1.y, acc1.y);
        acc1.z = fmaf(xi, w1.z, acc1.z); acc1.w = fmaf(xi, w1.w, acc1.w);
        bacc = fmaf(xi, sWc[i * HD + o], bacc);
    }

    __half2 hy[4];
    hy[0] = __floats2half2_rn(acc0.x, acc0.y);
    hy[1] = __floats2half2_rn(acc0.z, acc0.w);
    hy[2] = __floats2half2_rn(acc1.x, acc1.y);
    hy[3] = __floats2half2_rn(acc1.z, acc1.w);
    *(uint4*)(g_Yh + n * 32 + o * 4) = *(const uint4*)hy;
    g_base[gid] = bacc;
}

// Edge scatter: 8 lanes/edge, 4 edges/thread. PDL-dependent: all input
// (ei/ea) loads + half2 packing issue BEFORE cudaGridDependencySynchronize()
// and overlap the predecessor's tail; only the Y gathers (predecessor's
// output) and REDs come after. Dot in half2 (Y already fp16): 4 cvt-pack +
// 4 HFMA2 + 1 cvt vs 16 cvt + 8 FMA.
__global__ void __launch_bounds__(256, 4)
k_edge(const int* __restrict__ ei, const float* __restrict__ ea, int layer) {
    const int Q = NE / 4;
    int gid = blockIdx.x * blockDim.x + threadIdx.x;
    int r = gid & 7;
    int t = gid >> 3;             // [0, NE/4)
    int e0 = t, e1 = t + Q, e2 = t + 2 * Q, e3 = t + 3 * Q;

    int src0 = __ldg(ei + e0);
    int src1 = __ldg(ei + e1);
    int src2 = __ldg(ei + e2);
    int src3 = __ldg(ei + e3);
    int dst0 = __ldg(ei + NE + e0);
    int dst1 = __ldg(ei + NE + e1);
    int dst2 = __ldg(ei + NE + e2);
    int dst3 = __ldg(ei + NE + e3);
    float4 a00 = __ldg((const float4*)(ea + e0 * FE));
    float4 a01 = __ldg((const float4*)(ea + e0 * FE + 4));
    float4 a10 = __ldg((const float4*)(ea + e1 * FE));
    float4 a11 = __ldg((const float4*)(ea + e1 * FE + 4));
    float4 a20 = __ldg((const float4*)(ea + e2 * FE));
    float4 a21 = __ldg((const float4*)(ea + e2 * FE + 4));
    float4 a30 = __ldg((const float4*)(ea + e3 * FE));
    float4 a31 = __ldg((const float4*)(ea + e3 * FE + 4));

    // pack ea to half2 pre-sync (independent of predecessor output)
    __half2 eh[4][4];
    #define PACK_EA(k, A0, A1)                          \
        eh[k][0] = __floats2half2_rn((A0).x, (A0).y);   \
        eh[k][1] = __floats2half2_rn((A0).z, (A0).w);   \
        eh[k][2] = __floats2half2_rn((A1).x, (A1).y);   \
        eh[k][3] = __floats2half2_rn((A1).z, (A1).w);
    PACK_EA(0, a00, a01) PACK_EA(1, a10, a11)
    PACK_EA(2, a20, a21) PACK_EA(3, a30, a31)
    #undef PACK_EA

    // wait for predecessor (writer of g_Yh / zeroer of agg) to complete
    cudaGridDependencySynchronize();

    uint4 yq0 = __ldg((const uint4*)(g_Yh + src0 * 32 + r * 4));
    uint4 yq1 = __ldg((const uint4*)(g_Yh + src1 * 32 + r * 4));
    uint4 yq2 = __ldg((const uint4*)(g_Yh + src2 * 32 + r * 4));
    uint4 yq3 = __ldg((const uint4*)(g_Yh + src3 * 32 + r * 4));

    const unsigned FULL = 0xffffffffu;
    int lane = threadIdx.x & 31;
    float* aggL = g_agg[layer];

    #define EDGE_EMIT(yq, k, dst)                                               \
    {                                                                           \
        const __half2* yh = (const __half2*)&(yq);                              \
        __half2 hac = __hmul2(eh[k][0], yh[0]);                                 \
        hac = __hfma2(eh[k][1], yh[1], hac);                                    \
        hac = __hfma2(eh[k][2], yh[2], hac);                                    \
        hac = __hfma2(eh[k][3], yh[3], hac);                                    \
        float2 fa = __half22float2(hac);                                        \
        float m = fa.x + fa.y;                                                  \
        float ma = __shfl_sync(FULL, m, (lane + 1) & 31);                       \
        float mb = __shfl_sync(FULL, m, (lane + 2) & 31);                       \
        float mc = __shfl_sync(FULL, m, (lane + 3) & 31);                       \
        if ((r & 3) == 0) {                                                     \
            float* p = aggL + (dst) * HD + r;                                   \
            asm volatile("red.global.add.v4.f32 [%0], {%1, %2, %3, %4};"        \
                         :: "l"(p), "f"(m), "f"(ma), "f"(mb), "f"(mc)           \
                         : "memory");                                           \
        }                                                                       \
    }

    EDGE_EMIT(yq0, 0, dst0)
    EDGE_EMIT(yq1, 1, dst1)
    EDGE_EMIT(yq2, 2, dst2)
    EDGE_EMIT(yq3, 3, dst3)
    #undef EDGE_EMIT
}

// h1 = relu(agg1 + base1); layer-2 per-node precompute (thread per (n,o)).
// PDL-dependent: smem weight staging + agg[1] zeroing run pre-sync.
__global__ void k_node2(const float* __restrict__ We2, const float* __restrict__ be2,
                        const float* __restrict__ root2, const float* __restrict__ b2) {
    __shared__ float sW[HD * HD * HD];    // [i][o][a]
    __shared__ float sWc[HD * HD];        // root2 + be2 : [i][o]
    for (int t = threadIdx.x; t < HD * 64; t += blockDim.x) {
        int i = t >> 6, o = (t >> 3) & 7, a = t & 7;
        sW[t] = We2[a * (HD * HD) + i * HD + o];
    }
    for (int t = threadIdx.x; t < HD * HD; t += blockDim.x)
        sWc[t] = root2[t] + be2[t];

    int gid = blockIdx.x * blockDim.x + threadIdx.x;
    // zero agg[1] pre-sync: nothing before k_edge layer-1 touches it
    if (gid < NN * 2)
        ((float4*)g_agg[1])[gid] = make_float4(0.f, 0.f, 0.f, 0.f);
    __syncthreads();

    cudaGridDependencySynchronize();   // wait for k_edge layer-0 REDs

    int n = gid >> 3, o = gid & 7;
    if (n >= NN) return;

    float h[HD];
    {
        const float4* ap = (const float4*)(g_agg[0] + n * HD);
        const float4* cp = (const float4*)(g_base + n * HD);
        float4 a0 = ap[0], a1 = ap[1], c0 = cp[0], c1 = cp[1];
        h[0] = fmaxf(a0.x + c0.x, 0.f); h[1] = fmaxf(a0.y + c0.y, 0.f);
        h[2] = fmaxf(a0.z + c0.z, 0.f); h[3] = fmaxf(a0.w + c0.w, 0.f);
        h[4] = fmaxf(a1.x + c1.x, 0.f); h[5] = fmaxf(a1.y + c1.y, 0.f);
        h[6] = fmaxf(a1.z + c1.z, 0.f); h[7] = fmaxf(a1.w + c1.w, 0.f);
    }
    __syncwarp();   // all reads of g_base[n][*] done before warp-mates overwrite

    float4 acc0 = make_float4(0.f, 0.f, 0.f, 0.f);
    float4 acc1 = make_float4(0.f, 0.f, 0.f, 0.f);
    float bacc = __ldg(b2 + o);
    const float4* sW4 = (const float4*)sW;
    #pragma unroll
    for (int i = 0; i < HD; i++) {
        float hi = h[i];
        float4 w0 = sW4[(i * HD + o) * 2 + 0];
        float4 w1 = sW4[(i * HD + o) * 2 + 1];
        acc0.x = fmaf(hi, w0.x, acc0.x); acc0.y = fmaf(hi, w0.y, acc0.y);
        acc0.z = fmaf(hi, w0.z, acc0.z); acc0.w = fmaf(hi, w0.w, acc0.w);
        acc1.x = fmaf(hi, w1.x, acc1.x); acc1.y = fmaf(hi, w1.y, acc1.y);
        acc1.z = fmaf(hi, w1.z, acc1.z); acc1.w = fmaf(hi, w1.w, acc1.w);
        bacc = fmaf(hi, sWc[i * HD + o], bacc);
    }

    __half2 hy[4];
    hy[0] = __floats2half2_rn(acc0.x, acc0.y);
    hy[1] = __floats2half2_rn(acc0.z, acc0.w);
    hy[2] = __floats2half2_rn(acc1.x, acc1.y);
    hy[3] = __floats2half2_rn(acc1.z, acc1.w);
    *(uint4*)(g_Yh + n * 32 + o * 4) = *(const uint4*)hy;
    g_base[gid] = bacc;
}

// h2 = relu(agg2 + base2); out[batch[n]] += sum_o h2[o]*Wlast[o].
// batch SORTED -> warp-segmented reduction. PDL-dependent: batch/Wlast
// loads pre-sync.
__global__ void k_pool(const int* __restrict__ batch, const float* __restrict__ Wlast,
                       float* __restrict__ out) {
    int n = blockIdx.x * blockDim.x + threadIdx.x;
    int lane = threadIdx.x & 31;
    int bid = -1;
    if (n < NN) bid = __ldg(batch + n);
    float w0 = __ldg(Wlast + 0), w1 = __ldg(Wlast + 1);
    float w2 = __ldg(Wlast + 2), w3 = __ldg(Wlast + 3);
    float w4 = __ldg(Wlast + 4), w5 = __ldg(Wlast + 5);
    float w6 = __ldg(Wlast + 6), w7 = __ldg(Wlast + 7);

    cudaGridDependencySynchronize();   // wait for k_edge layer-1 REDs

    float s = 0.f;
    if (n < NN) {
        const float4* ap = (const float4*)(g_agg[1] + n * HD);
        const float4* cp = (const float4*)(g_base + n * HD);
        float4 a0 = ap[0], a1 = ap[1], c0 = cp[0], c1 = cp[1];
        s = fmaxf(a0.x + c0.x, 0.f) * w0 + fmaxf(a0.y + c0.y, 0.f) * w1
          + fmaxf(a0.z + c0.z, 0.f) * w2 + fmaxf(a0.w + c0.w, 0.f) * w3
          + fmaxf(a1.x + c1.x, 0.f) * w4 + fmaxf(a1.y + c1.y, 0.f) * w5
          + fmaxf(a1.z + c1.z, 0.f) * w6 + fmaxf(a1.w + c1.w, 0.f) * w7;
    }
    const unsigned FULL = 0xffffffffu;
    int bprev = __shfl_up_sync(FULL, bid, 1);
    #pragma unroll
    for (int d = 1; d < 32; d <<= 1) {
        float tv = __shfl_down_sync(FULL, s, d);
        int  tb = __shfl_down_sync(FULL, bid, d);
        if (lane + d < 32 && tb == bid) s += tv;
    }
    bool leader = (n < NN) && (lane == 0 || bprev != bid);
    if (leader) atomicAdd(out + bid, s);
}

template <typename F, typename... Args>
static void launch_pdl(F f, int grid, int block, Args... args) {
    cudaLaunchConfig_t cfg = {};
    cfg.gridDim = dim3(grid, 1, 1);
    cfg.blockDim = dim3(block, 1, 1);
    cfg.dynamicSmemBytes = 0;
    cfg.stream = 0;
    cudaLaunchAttribute at[1];
    at[0].id = cudaLaunchAttributeProgrammaticStreamSerialization;
    at[0].val.programmaticStreamSerializationAllowed = 1;
    cfg.attrs = at;
    cfg.numAttrs = 1;
    cudaLaunchKernelEx(&cfg, f, args...);
}

extern "C" void kernel_launch(void* const* d_in, const int* in_sizes, int n_in,
                              void* d_out, int out_size) {
    const float* x     = (const float*)d_in[0];
    const int*   ei    = (const int*)  d_in[1];
    const float* ea    = (const float*)d_in[2];
    const int*   batch = (const int*)  d_in[3];
    const float* We1   = (const float*)d_in[4];
    const float* be1   = (const float*)d_in[5];
    const float* root1 = (const float*)d_in[6];
    const float* b1    = (const float*)d_in[7];
    const float* We2   = (const float*)d_in[8];
    const float* be2   = (const float*)d_in[9];
    const float* root2 = (const float*)d_in[10];
    const float* b2    = (const float*)d_in[11];
    const float* Wlast = (const float*)d_in[12];
    const float* blast = (const float*)d_in[13];
    float* out = (float*)d_out;

    k_node1<<<(NN * HD + 255) / 256, 256>>>(x, We1, be1, root1, b1, blast, out);
    launch_pdl(k_edge,  (NE / 4) * 8 / 256, 256, ei, ea, 0);
    launch_pdl(k_node2, (NN * HD + 255) / 256, 256, We2, be2, root2, b2);
    launch_pdl(k_edge,  (NE / 4) * 8 / 256, 256, ei, ea, 1);
    launch_pdl(k_pool,  (NN + 255) / 256, 256, batch, Wlast, out);
}